// round 1
// baseline (speedup 1.0000x reference)
#include <cuda_runtime.h>

#define D      3072
#define BATCH  512
#define NC     100
#define RS     24      // row splits for column-sum kernel
#define RROWS  128     // rows per split (24*128 = 3072)
#define BK     64      // GEMM k-tile
#define NSPLIT 48      // D / BK
#define BM     64      // GEMM m-tile
#define MT     8       // BATCH / BM

// ---- device scratch (static, no allocation) ----
__device__ float g_pA[RS * D];
__device__ float g_pB[RS * D];
__device__ float g_colA[D];
__device__ float g_colB[D];
__device__ float g_fcrow[NC];
__device__ float g_part1;
__device__ float g_scratch[NSPLIT * BATCH * NC];   // 9.83 MB

// ============================================================
// K1: partial column sums of a and b.
// grid (12, 24, 2), block 256. Fully coalesced: consecutive threads
// read consecutive columns; each thread walks 128 rows (stride D).
// ============================================================
__global__ void k1_colsum_partial(const float* __restrict__ a,
                                  const float* __restrict__ b) {
    int d  = blockIdx.x * 256 + threadIdx.x;
    int rs = blockIdx.y;
    const float* src = (blockIdx.z == 0) ? a : b;
    float*       dst = (blockIdx.z == 0) ? g_pA : g_pB;
    const float* p = src + rs * RROWS * D + d;
    float acc = 0.f;
#pragma unroll 8
    for (int r = 0; r < RROWS; r++) acc += p[r * D];
    dst[rs * D + d] = acc;
}

// ============================================================
// K2: finalize column sums; fc_w row sums; scalar part1.
// grid 25 blocks x 256 threads.
//   blocks 0..11  : colA/colB (reduce 24 partials each)
//   blocks 12..24 : fc row sums (one warp per class c)
//   block 24 t0   : part1
// ============================================================
__global__ void k2_finalize(const float* __restrict__ fc_w,
                            const float* __restrict__ w,
                            const float* __restrict__ n_param) {
    int bx = blockIdx.x, t = threadIdx.x;
    if (bx < 12) {
        int d = bx * 256 + t;
        float sa = 0.f, sb = 0.f;
#pragma unroll
        for (int s = 0; s < RS; s++) {
            sa += g_pA[s * D + d];
            sb += g_pB[s * D + d];
        }
        g_colA[d] = sa;
        g_colB[d] = sb;
    } else {
        int c    = (bx - 12) * 8 + (t >> 5);
        int lane = t & 31;
        if (c < NC) {
            float s = 0.f;
            for (int j = lane; j < D; j += 32) s += fc_w[c * D + j];
#pragma unroll
            for (int o = 16; o; o >>= 1) s += __shfl_xor_sync(0xffffffffu, s, o);
            if (lane == 0) g_fcrow[c] = s;
        }
        if (bx == 24 && t == 0) {
            float p1 = 0.f;
#pragma unroll
            for (int i = 0; i < 4; i++)
                p1 += w[i + 1] * n_param[i + 1] + w[i] * n_param[i];
            g_part1 = p1;
        }
    }
}

// ============================================================
// K3: fused split-K GEMM.
//   Zpart[b,d] = cos(xf[b,d])*colA[d] + sin(xf[b,d])*colB[d]   (on the fly)
//   scratch[split][b][c] += Zpart-tile @ fc_w-tile^T
// grid (MT=8, NSPLIT=48), block 160 threads (5 warps).
// Thread micro-tile 8x5 -> 13 LDS per 40 FMA.
// Zs padded to 65 (2-way max), Wf padded to 68 (conflict-free + f4-aligned).
// Epilogue staged through smem for coalesced global stores.
// ============================================================
__global__ __launch_bounds__(160, 4)
void k3_gemm(const float* __restrict__ xf, const float* __restrict__ fc_w) {
    __shared__ float Zs[BM * (BK + 1)];       // [row][k], stride 65
    __shared__ float Wbuf[NC * (BK + 4)];     // [c][k], stride 68; reused as out tile

    const int mtile = blockIdx.x;
    const int split = blockIdx.y;
    const int t     = threadIdx.x;
    const int k0    = split * BK;

    // ---- load Z tile (compute cos/sin fused) ----
    for (int i = t; i < BM * (BK / 4); i += 160) {
        int row = i >> 4;          // BK/4 = 16
        int kq  = i & 15;
        float4 v = *reinterpret_cast<const float4*>(
            xf + (mtile * BM + row) * D + k0 + kq * 4);
        float vv[4] = {v.x, v.y, v.z, v.w};
#pragma unroll
        for (int j = 0; j < 4; j++) {
            int kk = kq * 4 + j;
            float sn, cs;
            __sincosf(vv[j], &sn, &cs);
            Zs[row * (BK + 1) + kk] =
                cs * g_colA[k0 + kk] + sn * g_colB[k0 + kk];
        }
    }
    // ---- load W tile ----
    for (int i = t; i < NC * (BK / 4); i += 160) {
        int c  = i >> 4;
        int kq = i & 15;
        float4 v = *reinterpret_cast<const float4*>(fc_w + c * D + k0 + kq * 4);
        *reinterpret_cast<float4*>(&Wbuf[c * (BK + 4) + kq * 4]) = v;
    }
    __syncthreads();

    const int rg = t & 7;    // 8 row groups (TM = 8)
    const int cg = t >> 3;   // 20 col groups (TN = 5)

    float acc[8][5];
#pragma unroll
    for (int m = 0; m < 8; m++)
#pragma unroll
        for (int n = 0; n < 5; n++) acc[m][n] = 0.f;

#pragma unroll 4
    for (int k = 0; k < BK; k++) {
        float zr[8], wv[5];
#pragma unroll
        for (int m = 0; m < 8; m++) zr[m] = Zs[(rg * 8 + m) * (BK + 1) + k];
#pragma unroll
        for (int n = 0; n < 5; n++) wv[n] = Wbuf[(cg * 5 + n) * (BK + 4) + k];
#pragma unroll
        for (int m = 0; m < 8; m++)
#pragma unroll
            for (int n = 0; n < 5; n++) acc[m][n] += zr[m] * wv[n];
    }

    // ---- stage output tile in smem (reuse Wbuf; stride 101 -> <=2-way) ----
    __syncthreads();
#pragma unroll
    for (int m = 0; m < 8; m++)
#pragma unroll
        for (int n = 0; n < 5; n++)
            Wbuf[(rg * 8 + m) * 101 + (cg * 5 + n)] = acc[m][n];
    __syncthreads();

    // ---- coalesced store to split scratch ----
    float* dst = g_scratch + split * (BATCH * NC) + mtile * (BM * NC);
    for (int i = t; i < BM * NC; i += 160) {
        int row = i / NC;
        int c   = i - row * NC;
        dst[i] = Wbuf[row * 101 + c];
    }
}

// ============================================================
// K4: reduce splits + part1 * rowsum(fc_w) + fc_b -> out[b][c]
// grid 200 blocks x 256.
// ============================================================
__global__ void k4_final(const float* __restrict__ fc_b, float* __restrict__ out) {
    int idx = blockIdx.x * 256 + threadIdx.x;
    if (idx >= BATCH * NC) return;
    int c = idx % NC;
    float s = 0.f;
#pragma unroll 8
    for (int sp = 0; sp < NSPLIT; sp++) s += g_scratch[sp * (BATCH * NC) + idx];
    out[idx] = s + g_part1 * g_fcrow[c] + fc_b[c];
}

// ============================================================
extern "C" void kernel_launch(void* const* d_in, const int* in_sizes, int n_in,
                              void* d_out, int out_size) {
    const float* x       = (const float*)d_in[0];   // [512,3,32,32] == [512,3072]
    const float* a       = (const float*)d_in[1];   // [3072,3072,1]
    const float* b       = (const float*)d_in[2];   // [3072,3072,1]
    const float* w       = (const float*)d_in[3];   // [5]
    const float* n_param = (const float*)d_in[4];   // [5]
    const float* fc_w    = (const float*)d_in[5];   // [100,3072]
    const float* fc_b    = (const float*)d_in[6];   // [100]
    float* out = (float*)d_out;                     // [512,100]

    k1_colsum_partial<<<dim3(12, RS, 2), 256>>>(a, b);
    k2_finalize<<<25, 256>>>(fc_w, w, n_param);
    k3_gemm<<<dim3(MT, NSPLIT), 160>>>(x, fc_w);
    k4_final<<<200, 256>>>(fc_b, out);
}